// round 11
// baseline (speedup 1.0000x reference)
#include <cuda_runtime.h>
#include <cuda_bf16.h>

#define NNODES 512
#define NIN    256
#define NOUT   256
#define NT     32      // 512/16 node tiles
#define TS     16      // writer tile size

// Split-K partial buffers: A = A0 + A1 (bias folded into A0), B = B0 + B1.
__device__ float g_A0[NNODES * NOUT];
__device__ float g_A1[NNODES * NOUT];
__device__ float g_B0[NNODES * NOUT];
__device__ float g_B1[NNODES * NOUT];

// Per-32-row-group readiness flags (16 groups of 32 rows). A group is ready
// when all 8 (o-tiles) x 2 (K-splits) = 16 producer units have signalled.
__device__ int g_flagA[16];
__device__ int g_flagB[16];
__device__ int g_done;     // completion counter for end-of-launch flag reset

__device__ __forceinline__ int ld_acquire(const int* p) {
    int v;
    asm volatile("ld.acquire.gpu.global.s32 %0, [%1];" : "=r"(v) : "l"(p) : "memory");
    return v;
}
__device__ __forceinline__ void red_release_add(int* p, int v) {
    asm volatile("red.release.gpu.global.add.s32 [%0], %1;" :: "l"(p), "r"(v) : "memory");
}

// ---------------------------------------------------------------------------
// Fused kernel: GEMM producers (lowest 256 bids, 2 units each) + symmetric
// tile writer (all 1024 blocks), synchronized via per-group flags.
// ---------------------------------------------------------------------------
__global__ void __launch_bounds__(256)
fused_kernel(const float* __restrict__ x,
             const float* __restrict__ W,
             const float* __restrict__ b,
             float* __restrict__ out)
{
    // 16 KB shared pool: gemm uses the first 2240 floats (xs:1088 + ws:1152),
    // writer uses all 4096 for the B tile. Phases separated by __syncthreads.
    __shared__ __align__(16) float smem_pool[TS * NOUT];

    const int tid = threadIdx.x;
    const int bid = blockIdx.y * NT + blockIdx.x;   // dispatch-order linear id

    // ==================== GEMM phase (producer blocks) =====================
    if (bid < 256) {
        float* xs = smem_pool;           // [k][i] stride 34, 1088 floats
        float* ws = smem_pool + 1088;    // [k][o] stride 36, 1152 floats

        const int lr = tid >> 3;         // load row 0..31
        const int lq = tid & 7;          // load k-quad 0..7
        const int ty = tid >> 3;         // compute: i row 0..31
        const int tx = tid & 7;          // compute: o quad 0..7

        #pragma unroll
        for (int u = 0; u < 2; u++) {
            const int unit = bid + u * 256;        // 0..511
            const int z    = unit >> 7;            // 0..3
            const int half = z >> 1;               // 0: A, 1: B
            const int ks   = z & 1;                // K-split
            const int by   = (unit >> 3) & 15;     // i tile (32 rows)
            const int bx   = unit & 7;             // o tile (32 cols)
            const int i0   = by * 32;
            const int o0   = bx * 32;
            const int kbase = ks * 128;
            const int woff  = half * NIN;

            // prefetch chunk 0
            float4 vx = *reinterpret_cast<const float4*>(
                &x[(i0 + lr) * NIN + kbase + lq * 4]);
            float4 vw = *reinterpret_cast<const float4*>(
                &W[(o0 + lr) * (2 * NIN) + woff + kbase + lq * 4]);

            float acc[4] = {0.f, 0.f, 0.f, 0.f};

            #pragma unroll
            for (int ch = 0; ch < 4; ch++) {
                // scatter prefetched frags to smem (transposed)
                xs[(lq * 4 + 0) * 34 + lr] = vx.x;
                xs[(lq * 4 + 1) * 34 + lr] = vx.y;
                xs[(lq * 4 + 2) * 34 + lr] = vx.z;
                xs[(lq * 4 + 3) * 34 + lr] = vx.w;
                ws[(lq * 4 + 0) * 36 + lr] = vw.x;
                ws[(lq * 4 + 1) * 36 + lr] = vw.y;
                ws[(lq * 4 + 2) * 36 + lr] = vw.z;
                ws[(lq * 4 + 3) * 36 + lr] = vw.w;
                __syncthreads();

                if (ch < 3) {   // prefetch next chunk during compute
                    const int k0 = kbase + (ch + 1) * 32;
                    vx = *reinterpret_cast<const float4*>(
                        &x[(i0 + lr) * NIN + k0 + lq * 4]);
                    vw = *reinterpret_cast<const float4*>(
                        &W[(o0 + lr) * (2 * NIN) + woff + k0 + lq * 4]);
                }

                #pragma unroll
                for (int kk = 0; kk < 32; kk++) {
                    float  a  = xs[kk * 34 + ty];
                    float4 wq = *reinterpret_cast<const float4*>(&ws[kk * 36 + tx * 4]);
                    acc[0] += a * wq.x;
                    acc[1] += a * wq.y;
                    acc[2] += a * wq.z;
                    acc[3] += a * wq.w;
                }
                __syncthreads();
            }

            float4 bias = make_float4(0.f, 0.f, 0.f, 0.f);
            if (half == 0 && ks == 0)
                bias = *reinterpret_cast<const float4*>(&b[o0 + tx * 4]);

            float* dst = (half == 0) ? (ks == 0 ? g_A0 : g_A1)
                                     : (ks == 0 ? g_B0 : g_B1);
            float4 outv = make_float4(acc[0] + bias.x, acc[1] + bias.y,
                                      acc[2] + bias.z, acc[3] + bias.w);
            *reinterpret_cast<float4*>(&dst[(i0 + ty) * NOUT + o0 + tx * 4]) = outv;

            // signal group readiness (release)
            __threadfence();
            __syncthreads();
            if (tid == 0)
                red_release_add((half == 0 ? g_flagA : g_flagB) + by, 1);
        }
        __syncthreads();   // smem_pool handoff to writer phase
    }

    // ==================== Writer phase (all 1024 blocks) ===================
    int bj = blockIdx.x;
    int bi = blockIdx.y;
    bool mirror = false;
    if (bi > bj) {                    // remap lower -> strict-upper twin
        bi = (NT - 1) - bi;
        bj = (NT - 1) - bj;
        mirror = true;
    }
    const bool diag = (bi == bj);
    const int i0 = bi * TS;
    const int j0 = bj * TS;

    // wait for the A rows (group bi>>1) and B rows (group bj>>1)
    if (tid == 0) {
        while (ld_acquire(&g_flagA[bi >> 1]) < 16) __nanosleep(128);
        while (ld_acquire(&g_flagB[bj >> 1]) < 16) __nanosleep(128);
    }
    __syncthreads();

    float* sB = smem_pool;            // 16 KB B tile

    const int c  = (tid & 63) * 4;    // channel offset (float4 lane)
    const int ip = tid >> 6;          // ii sub-index 0..3

    // ---- A rows into registers (coalesced float4) ----
    float4 aR[4];
    #pragma unroll
    for (int ob = 0; ob < 4; ob++) {
        int r = i0 + ob * 4 + ip;
        float4 a0 = *reinterpret_cast<const float4*>(&g_A0[r * NOUT + c]);
        float4 a1 = *reinterpret_cast<const float4*>(&g_A1[r * NOUT + c]);
        aR[ob] = make_float4(a0.x + a1.x, a0.y + a1.y, a0.z + a1.z, a0.w + a1.w);
    }

    // ---- B tile (B0+B1) into smem, float4 coalesced ----
    #pragma unroll
    for (int s = 0; s < 4; s++) {
        int idx = tid + s * 256;      // float4 slot 0..1023
        int r   = idx >> 6;           // row 0..15
        int cc  = (idx & 63) * 4;
        float4 b0 = *reinterpret_cast<const float4*>(&g_B0[(j0 + r) * NOUT + cc]);
        float4 b1 = *reinterpret_cast<const float4*>(&g_B1[(j0 + r) * NOUT + cc]);
        *reinterpret_cast<float4*>(&sB[r * NOUT + cc]) =
            make_float4(b0.x + b1.x, b0.y + b1.y, b0.z + b1.z, b0.w + b1.w);
    }
    __syncthreads();

    if (!diag) {
        const size_t stride = mirror ? (size_t)NNODES * NOUT : (size_t)NOUT;
        #pragma unroll
        for (int ob = 0; ob < 4; ob++) {
            const int ii = ob * 4 + ip;
            const int i  = i0 + ii;
            const float4 a = aR[ob];
            float* p = mirror
                ? &out[((size_t)j0 * NNODES + i) * NOUT + c]
                : &out[((size_t)i * NNODES + j0) * NOUT + c];
            #pragma unroll 4
            for (int jj = 0; jj < TS; jj++) {
                float4 bb = *reinterpret_cast<const float4*>(&sB[jj * NOUT + c]);
                float4 v  = make_float4(a.x + bb.x, a.y + bb.y,
                                        a.z + bb.z, a.w + bb.w);
                __stcs(reinterpret_cast<float4*>(p), v);
                p += stride;
            }
        }
    } else {
        // diagonal tile: single block writes both copies + zero diagonal
        #pragma unroll
        for (int ob = 0; ob < 4; ob++) {
            const int ii = ob * 4 + ip;
            const int i  = i0 + ii;
            const float4 a = aR[ob];
            float* pij = &out[((size_t)i * NNODES + (j0 + ii + 1)) * NOUT + c];
            float* pji = &out[((size_t)(j0 + ii + 1) * NNODES + i) * NOUT + c];
            for (int jj = ii + 1; jj < TS; jj++) {
                float4 bb = *reinterpret_cast<const float4*>(&sB[jj * NOUT + c]);
                float4 v  = make_float4(a.x + bb.x, a.y + bb.y,
                                        a.z + bb.z, a.w + bb.w);
                __stcs(reinterpret_cast<float4*>(pij), v);
                __stcs(reinterpret_cast<float4*>(pji), v);
                pij += NOUT;
                pji += (size_t)NNODES * NOUT;
            }
            __stcs(reinterpret_cast<float4*>(
                &out[((size_t)i * NNODES + i) * NOUT + c]),
                make_float4(0.f, 0.f, 0.f, 0.f));
        }
    }

    // ---- last block resets flags for the next graph replay ----
    __syncthreads();
    if (tid == 0) {
        int old = atomicAdd(&g_done, 1);
        if (old == NT * NT - 1) {
            #pragma unroll
            for (int g = 0; g < 16; g++) { g_flagA[g] = 0; g_flagB[g] = 0; }
            __threadfence();
            atomicExch(&g_done, 0);
        }
    }
}

extern "C" void kernel_launch(void* const* d_in, const int* in_sizes, int n_in,
                              void* d_out, int out_size)
{
    const float* x = (const float*)d_in[0];   // [512, 256]
    const float* W = (const float*)d_in[1];   // [256, 512]
    const float* b = (const float*)d_in[2];   // [256]
    float* out = (float*)d_out;               // [512, 512, 256]

    fused_kernel<<<dim3(NT, NT), 256>>>(x, W, b, out);
}

// round 12
// speedup vs baseline: 1.2549x; 1.2549x over previous
#include <cuda_runtime.h>
#include <cuda_bf16.h>

#define NNODES 512
#define NIN    256
#define NOUT   256
#define NT     32      // 512/16 node tiles
#define TS     16      // writer tile size

// Split-K partial buffers: A = A0 + A1 (bias folded into A0), B = B0 + B1.
__device__ float g_A0[NNODES * NOUT];
__device__ float g_A1[NNODES * NOUT];
__device__ float g_B0[NNODES * NOUT];
__device__ float g_B1[NNODES * NOUT];

// ---------------------------------------------------------------------------
// Kernel 1: split-K GEMM partials, 64x64x32 tiles, 4x4 micro-tile,
// register double-buffered K chunks. 128 blocks x 256 threads.
//   z = half*2 + ks. C_part[i,o] = sum_{k in chunk ks} x[i,k]*W[o, half*256+k]
// ---------------------------------------------------------------------------
__global__ void __launch_bounds__(256)
gemm_ab_kernel(const float* __restrict__ x,
               const float* __restrict__ W,
               const float* __restrict__ b)
{
    const int z    = blockIdx.z;
    const int half = z >> 1;                  // 0: A, 1: B
    const int ks   = z & 1;                   // K-split index
    const int i0   = blockIdx.y * 64;
    const int o0   = blockIdx.x * 64;
    const int kbase = ks * 128;
    const int woff  = half * NIN;

    // [k][i] and [k][o], stride 68 floats (272B: float4-aligned, no conflicts)
    __shared__ __align__(16) float xs[32 * 68];
    __shared__ __align__(16) float ws[32 * 68];

    const int tid = threadIdx.x;
    const int tx  = tid & 15;   // o-thread: 4 cols  -> 64 o
    const int ty  = tid >> 4;   // i-thread: 4 rows  -> 64 i

    // per-thread load coords: 2 float4 slots per tile (512 slots / 256 thr)
    const int lr0 = tid >> 2;              // rows 0..63  (slot = tid)
    const int lq0 = (tid & 3) * 2;         // k-quads {0,2,4,6}
    const int lq1 = lq0 + 1;               // k-quads {1,3,5,7}

    float4 vx[2][2], vw[2][2];

    // prefetch chunk 0
    {
        const float* px = &x[(i0 + lr0) * NIN + kbase];
        const float* pw = &W[(o0 + lr0) * (2 * NIN) + woff + kbase];
        vx[0][0] = *reinterpret_cast<const float4*>(px + lq0 * 4);
        vx[0][1] = *reinterpret_cast<const float4*>(px + lq1 * 4);
        vw[0][0] = *reinterpret_cast<const float4*>(pw + lq0 * 4);
        vw[0][1] = *reinterpret_cast<const float4*>(pw + lq1 * 4);
    }

    float acc[4][4];
    #pragma unroll
    for (int r = 0; r < 4; r++)
        #pragma unroll
        for (int q = 0; q < 4; q++) acc[r][q] = 0.f;

    #pragma unroll
    for (int ch = 0; ch < 4; ch++) {
        const int cur = ch & 1;
        // scatter prefetched regs into smem (transposed)
        {
            float4 v = vx[cur][0];
            xs[(lq0 * 4 + 0) * 68 + lr0] = v.x;
            xs[(lq0 * 4 + 1) * 68 + lr0] = v.y;
            xs[(lq0 * 4 + 2) * 68 + lr0] = v.z;
            xs[(lq0 * 4 + 3) * 68 + lr0] = v.w;
            v = vx[cur][1];
            xs[(lq1 * 4 + 0) * 68 + lr0] = v.x;
            xs[(lq1 * 4 + 1) * 68 + lr0] = v.y;
            xs[(lq1 * 4 + 2) * 68 + lr0] = v.z;
            xs[(lq1 * 4 + 3) * 68 + lr0] = v.w;
            v = vw[cur][0];
            ws[(lq0 * 4 + 0) * 68 + lr0] = v.x;
            ws[(lq0 * 4 + 1) * 68 + lr0] = v.y;
            ws[(lq0 * 4 + 2) * 68 + lr0] = v.z;
            ws[(lq0 * 4 + 3) * 68 + lr0] = v.w;
            v = vw[cur][1];
            ws[(lq1 * 4 + 0) * 68 + lr0] = v.x;
            ws[(lq1 * 4 + 1) * 68 + lr0] = v.y;
            ws[(lq1 * 4 + 2) * 68 + lr0] = v.z;
            ws[(lq1 * 4 + 3) * 68 + lr0] = v.w;
        }
        __syncthreads();

        // prefetch next chunk while computing on smem
        if (ch < 3) {
            const int nxt = cur ^ 1;
            const int k0  = kbase + (ch + 1) * 32;
            const float* px = &x[(i0 + lr0) * NIN + k0];
            const float* pw = &W[(o0 + lr0) * (2 * NIN) + woff + k0];
            vx[nxt][0] = *reinterpret_cast<const float4*>(px + lq0 * 4);
            vx[nxt][1] = *reinterpret_cast<const float4*>(px + lq1 * 4);
            vw[nxt][0] = *reinterpret_cast<const float4*>(pw + lq0 * 4);
            vw[nxt][1] = *reinterpret_cast<const float4*>(pw + lq1 * 4);
        }

        #pragma unroll
        for (int kk = 0; kk < 32; kk++) {
            float4 aq = *reinterpret_cast<const float4*>(&xs[kk * 68 + ty * 4]);
            float4 wq = *reinterpret_cast<const float4*>(&ws[kk * 68 + tx * 4]);
            acc[0][0] += aq.x * wq.x; acc[0][1] += aq.x * wq.y;
            acc[0][2] += aq.x * wq.z; acc[0][3] += aq.x * wq.w;
            acc[1][0] += aq.y * wq.x; acc[1][1] += aq.y * wq.y;
            acc[1][2] += aq.y * wq.z; acc[1][3] += aq.y * wq.w;
            acc[2][0] += aq.z * wq.x; acc[2][1] += aq.z * wq.y;
            acc[2][2] += aq.z * wq.z; acc[2][3] += aq.z * wq.w;
            acc[3][0] += aq.w * wq.x; acc[3][1] += aq.w * wq.y;
            acc[3][2] += aq.w * wq.z; acc[3][3] += aq.w * wq.w;
        }
        __syncthreads();
    }

    float4 bias = make_float4(0.f, 0.f, 0.f, 0.f);
    if (half == 0 && ks == 0)
        bias = *reinterpret_cast<const float4*>(&b[o0 + tx * 4]);

    float* dst = (half == 0) ? (ks == 0 ? g_A0 : g_A1)
                             : (ks == 0 ? g_B0 : g_B1);
    #pragma unroll
    for (int r = 0; r < 4; r++) {
        int i = i0 + ty * 4 + r;
        float4 outv = make_float4(acc[r][0] + bias.x,
                                  acc[r][1] + bias.y,
                                  acc[r][2] + bias.z,
                                  acc[r][3] + bias.w);
        *reinterpret_cast<float4*>(&dst[i * NOUT + o0 + tx * 4]) = outv;
    }

    // PDL: writes above are visible to the dependent grid's griddepcontrol.wait
    asm volatile("griddepcontrol.launch_dependents;" ::: "memory");
}

// ---------------------------------------------------------------------------
// Kernel 2: symmetric tile writer — EXACT R7 version (41.7us measured).
//   - All 1024 blocks active via lower->upper remap (mirror-writer twin).
//   - A rows in registers, B tile in 16 KB smem.
//   - Pointer-increment addressing; __stcs streaming stores.
//   - PDL wait before first global read.
// ---------------------------------------------------------------------------
__global__ void __launch_bounds__(256)
sym_writer_kernel(float* __restrict__ out)
{
    int bj = blockIdx.x;
    int bi = blockIdx.y;
    bool mirror = false;
    if (bi > bj) {                    // remap lower -> strict-upper twin
        bi = (NT - 1) - bi;
        bj = (NT - 1) - bj;
        mirror = true;
    }
    const bool diag = (bi == bj);
    const int i0 = bi * TS;
    const int j0 = bj * TS;

    __shared__ __align__(16) float sB[TS * NOUT];    // 16 KB

    const int tid = threadIdx.x;
    const int c   = (tid & 63) * 4;   // channel offset (float4 lane)
    const int ip  = tid >> 6;         // ii sub-index 0..3

    // Wait until the GEMM grid's writes to g_* are visible.
    asm volatile("griddepcontrol.wait;" ::: "memory");

    // ---- A rows into registers: ii = ob*4 + ip, coalesced float4 loads ----
    float4 aR[4];
    #pragma unroll
    for (int ob = 0; ob < 4; ob++) {
        int r = i0 + ob * 4 + ip;
        float4 a0 = *reinterpret_cast<const float4*>(&g_A0[r * NOUT + c]);
        float4 a1 = *reinterpret_cast<const float4*>(&g_A1[r * NOUT + c]);
        aR[ob] = make_float4(a0.x + a1.x, a0.y + a1.y, a0.z + a1.z, a0.w + a1.w);
    }

    // ---- B tile (B0+B1) into smem, float4 coalesced ----
    #pragma unroll
    for (int s = 0; s < 4; s++) {
        int idx = tid + s * 256;      // float4 slot 0..1023
        int r   = idx >> 6;           // row 0..15
        int cc  = (idx & 63) * 4;
        float4 b0 = *reinterpret_cast<const float4*>(&g_B0[(j0 + r) * NOUT + cc]);
        float4 b1 = *reinterpret_cast<const float4*>(&g_B1[(j0 + r) * NOUT + cc]);
        *reinterpret_cast<float4*>(&sB[r * NOUT + cc]) =
            make_float4(b0.x + b1.x, b0.y + b1.y, b0.z + b1.z, b0.w + b1.w);
    }
    __syncthreads();

    if (!diag) {
        const size_t stride = mirror ? (size_t)NNODES * NOUT : (size_t)NOUT;
        #pragma unroll
        for (int ob = 0; ob < 4; ob++) {
            const int ii = ob * 4 + ip;
            const int i  = i0 + ii;
            const float4 a = aR[ob];
            float* p = mirror
                ? &out[((size_t)j0 * NNODES + i) * NOUT + c]
                : &out[((size_t)i * NNODES + j0) * NOUT + c];
            #pragma unroll 4
            for (int jj = 0; jj < TS; jj++) {
                float4 bb = *reinterpret_cast<const float4*>(&sB[jj * NOUT + c]);
                float4 v  = make_float4(a.x + bb.x, a.y + bb.y,
                                        a.z + bb.z, a.w + bb.w);
                __stcs(reinterpret_cast<float4*>(p), v);
                p += stride;
            }
        }
    } else {
        // diagonal tile: single block writes both copies + zero diagonal
        #pragma unroll
        for (int ob = 0; ob < 4; ob++) {
            const int ii = ob * 4 + ip;
            const int i  = i0 + ii;
            const float4 a = aR[ob];
            float* pij = &out[((size_t)i * NNODES + (j0 + ii + 1)) * NOUT + c];
            float* pji = &out[((size_t)(j0 + ii + 1) * NNODES + i) * NOUT + c];
            for (int jj = ii + 1; jj < TS; jj++) {
                float4 bb = *reinterpret_cast<const float4*>(&sB[jj * NOUT + c]);
                float4 v  = make_float4(a.x + bb.x, a.y + bb.y,
                                        a.z + bb.z, a.w + bb.w);
                __stcs(reinterpret_cast<float4*>(pij), v);
                __stcs(reinterpret_cast<float4*>(pji), v);
                pij += NOUT;
                pji += (size_t)NNODES * NOUT;
            }
            __stcs(reinterpret_cast<float4*>(
                &out[((size_t)i * NNODES + i) * NOUT + c]),
                make_float4(0.f, 0.f, 0.f, 0.f));
        }
    }
}

extern "C" void kernel_launch(void* const* d_in, const int* in_sizes, int n_in,
                              void* d_out, int out_size)
{
    const float* x = (const float*)d_in[0];   // [512, 256]
    const float* W = (const float*)d_in[1];   // [256, 512]
    const float* b = (const float*)d_in[2];   // [256]
    float* out = (float*)d_out;               // [512, 512, 256]

    // Kernel 1: split-K partials, 64x64 tiles (128 blocks x 256 threads)
    gemm_ab_kernel<<<dim3(4, 8, 4), 256>>>(x, W, b);

    // Kernel 2: symmetric writer with PDL overlap of the GEMM tail.
    cudaLaunchConfig_t cfg = {};
    cfg.gridDim  = dim3(NT, NT, 1);
    cfg.blockDim = dim3(256, 1, 1);
    cfg.dynamicSmemBytes = 0;
    cfg.stream = 0;
    cudaLaunchAttribute attrs[1];
    attrs[0].id = cudaLaunchAttributeProgrammaticStreamSerialization;
    attrs[0].val.programmaticStreamSerializationAllowed = 1;
    cfg.attrs = attrs;
    cfg.numAttrs = 1;
    cudaLaunchKernelEx(&cfg, sym_writer_kernel, out);
}